// round 7
// baseline (speedup 1.0000x reference)
#include <cuda_runtime.h>
#include <cuda_fp16.h>

// LocalPosEnc2D: bilinear grid sample (513x513 x 24ch, fp32) + sinusoidal PE gating.
//   coords: (B,2) fp32   grids: (513*513, 24) fp32   out: (B,24) fp32
// 6 lanes per point; lane j owns channels 4j..4j+3 (one float4 per corner row).
// Fast trig: frac-fold to [-pi,pi), MUFU sin/cos; ~1e-6 abs error, far under
// the fp16 output quantization (reference casts to float16).

#define GRID_ELEMS (513 * 513 * 24)
#define TWO_PI_F 6.28318530717958647692f
#define PI_F     3.14159265358979323846f

__global__ __launch_bounds__(192) void lpe2d_kernel(
    const float2* __restrict__ coords,
    const float4* __restrict__ grids,   // grid row = 6 float4 (24 floats)
    float4*       __restrict__ out,     // out row  = 6 float4 (24 floats)
    int B)
{
    int gtid = blockIdx.x * blockDim.x + threadIdx.x;
    int p = gtid / 6;          // point index
    int j = gtid - p * 6;      // chunk role 0..5 (channels 4j..4j+3)
    if (p >= B) return;

    float2 c = coords[p];      // 6 lanes same address -> broadcast
    float u = fminf(fmaxf(c.x, 0.0f), 1.0f - 1e-6f);
    float v = fminf(fmaxf(c.y, 0.0f), 1.0f - 1e-6f);
    float fu = u * 512.0f;
    float fv = v * 512.0f;
    int iu = (int)fu; iu = iu > 511 ? 511 : iu;
    int iv = (int)fv; iv = iv > 511 ? 511 : iv;
    float lu = fu - (float)iu;
    float lv = fv - (float)iv;

    int idx00 = iu + iv * 513;
    const float4* r0 = grids + (size_t)idx00 * 6;          // rows idx00, idx00+1 (192B)
    const float4* r1 = grids + (size_t)(idx00 + 513) * 6;  // rows idx01, idx01+1 (192B)

    // 4 independent 16B gathers; consecutive lanes in each 6-lane group hit
    // consecutive addresses -> few L1 wavefronts, exact 32B-sector use.
    float4 a  = r0[j];
    float4 bq = r0[j + 6];
    float4 cq = r1[j];
    float4 dq = r1[j + 6];

    // Gate PE for this lane's channels (lanes 0,1 = base channels: gate = 1).
    float pes[4] = {1.0f, 1.0f, 1.0f, 1.0f};
    if (j >= 2) {
        int g = j - 2;                       // 0:cos(lu) 1:sin(lu) 2:cos(lv) 3:sin(lv)
        float l = (g < 2) ? lu : lv;
        bool use_sin = (g & 1);
        float t = l;
#pragma unroll
        for (int k = 0; k < 4; k++) {
            float r = t - floorf(t);                 // frac(l * 2^k) in [0,1)
            float ang = fmaf(r, TWO_PI_F, -PI_F);    // [-pi, pi)
            // sin(2*pi*r) = -sin(ang); cos(2*pi*r) = -cos(ang)
            pes[k] = use_sin ? -__sinf(ang) : -__cosf(ang);
            t *= 2.0f;
        }
    }

    float wu0 = 1.0f - lu, wv0 = 1.0f - lv;
    const float* ap = (const float*)&a;
    const float* bp = (const float*)&bq;
    const float* cp = (const float*)&cq;
    const float* dp = (const float*)&dq;

    float4 o;
    float* op = (float*)&o;
#pragma unroll
    for (int w = 0; w < 4; w++) {
        float top = ap[w] * wu0 + bp[w] * lu;    // mirror reference expression
        float bot = cp[w] * wu0 + dp[w] * lu;
        float res = top * wv0 + bot * lv;
        res *= pes[w];
        // Reference casts its fp32 result to float16; match that rounding.
        op[w] = __half2float(__float2half_rn(res));
    }

    out[(size_t)p * 6 + j] = o;                  // fully coalesced 96B/point

}

extern "C" void kernel_launch(void* const* d_in, const int* in_sizes, int n_in,
                              void* d_out, int out_size) {
    // Bind inputs by size: grids has exactly 513*513*24 elements.
    int gi = -1, ci = -1;
    for (int i = 0; i < n_in; i++)
        if (in_sizes[i] == GRID_ELEMS && gi < 0) gi = i;
    for (int i = 0; i < n_in; i++)
        if (i != gi && ci < 0) ci = i;
    if (gi < 0) { gi = 1; ci = 0; }

    const float2* coords = (const float2*)d_in[ci];
    const float4* grids  = (const float4*)d_in[gi];
    float4*       out    = (float4*)d_out;
    int B = out_size / 24;                       // out is (B, 24) fp32
    long long threads_total = (long long)B * 6;
    int threads = 192;
    int blocks = (int)((threads_total + threads - 1) / threads);
    lpe2d_kernel<<<blocks, threads>>>(coords, grids, out, B);
}

// round 8
// speedup vs baseline: 1.4998x; 1.4998x over previous
#include <cuda_runtime.h>
#include <cuda_fp16.h>

// LocalPosEnc2D: bilinear grid sample (513x513 x 24ch, fp32) + sinusoidal PE gating.
//   coords: (B,2) fp32   grids: (513*513, 24) fp32   out: (B,24) fp32
// 6 lanes per point; lane j owns channels 4j..4j+3 (one float4 per corner row).
// Trig: 2 MUFU (sin/cos of 2*pi*l, folded to [-pi,pi)) + double-angle
// recurrences for freqs 2,4,8. All scalars — no arrays, nothing spills.

#define GRID_ELEMS (513 * 513 * 24)
#define TWO_PI_F 6.28318530717958647692f
#define PI_F     3.14159265358979323846f

__global__ __launch_bounds__(192) void lpe2d_kernel(
    const float2* __restrict__ coords,
    const float4* __restrict__ grids,   // grid row = 6 float4 (24 floats)
    float4*       __restrict__ out,     // out row  = 6 float4 (24 floats)
    int B)
{
    int gtid = blockIdx.x * blockDim.x + threadIdx.x;
    int p = gtid / 6;          // point index
    int j = gtid - p * 6;      // chunk role 0..5 (channels 4j..4j+3)
    if (p >= B) return;

    float2 c = coords[p];      // 6 lanes same address -> broadcast
    float u = fminf(fmaxf(c.x, 0.0f), 1.0f - 1e-6f);
    float v = fminf(fmaxf(c.y, 0.0f), 1.0f - 1e-6f);
    float fu = u * 512.0f;
    float fv = v * 512.0f;
    int iu = (int)fu; iu = iu > 511 ? 511 : iu;
    int iv = (int)fv; iv = iv > 511 ? 511 : iv;
    float lu = fu - (float)iu;
    float lv = fv - (float)iv;

    int idx00 = iu + iv * 513;
    const float4* r0 = grids + (size_t)idx00 * 6;          // rows idx00, idx00+1 (192B)
    const float4* r1 = grids + (size_t)(idx00 + 513) * 6;  // rows idx01, idx01+1 (192B)

    // 4 independent 16B gathers; consecutive lanes in each 6-lane group hit
    // consecutive addresses -> few L1 wavefronts, exact 32B-sector use.
    float4 a  = r0[j];
    float4 bq = r0[j + 6];
    float4 cq = r1[j];
    float4 dq = r1[j + 6];

    // PE gates for this lane's 4 channels. Lane roles:
    //  j=0,1: base channels (gate 1)
    //  j=2: cos(2^k*2pi*lu)  j=3: sin(..lu)  j=4: cos(..lv)  j=5: sin(..lv)
    float l = (j < 4) ? lu : lv;                 // j=2,3 -> lu ; j=4,5 -> lv
    float ang = fmaf(l, TWO_PI_F, -PI_F);        // in [-pi, pi)
    float s0 = -__sinf(ang);                     // sin(2*pi*l)
    float c0 = -__cosf(ang);                     // cos(2*pi*l)
    // double-angle recurrences (exact mod-2pi semantics)
    float s1 = 2.0f * s0 * c0;
    float c1 = fmaf(2.0f * c0, c0, -1.0f);
    float s2 = 2.0f * s1 * c1;
    float c2 = fmaf(2.0f * c1, c1, -1.0f);
    float s3 = 2.0f * s2 * c2;
    float c3 = fmaf(2.0f * c2, c2, -1.0f);

    bool use_sin = (j & 1);                      // j=3,5 -> sin ; j=2,4 -> cos
    float pe0 = use_sin ? s0 : c0;
    float pe1 = use_sin ? s1 : c1;
    float pe2 = use_sin ? s2 : c2;
    float pe3 = use_sin ? s3 : c3;
    if (j < 2) { pe0 = 1.0f; pe1 = 1.0f; pe2 = 1.0f; pe3 = 1.0f; }

    float wu0 = 1.0f - lu, wv0 = 1.0f - lv;

    float4 o;
    {
        float top = a.x * wu0 + bq.x * lu;
        float bot = cq.x * wu0 + dq.x * lu;
        o.x = __half2float(__float2half_rn((top * wv0 + bot * lv) * pe0));
    }
    {
        float top = a.y * wu0 + bq.y * lu;
        float bot = cq.y * wu0 + dq.y * lu;
        o.y = __half2float(__float2half_rn((top * wv0 + bot * lv) * pe1));
    }
    {
        float top = a.z * wu0 + bq.z * lu;
        float bot = cq.z * wu0 + dq.z * lu;
        o.z = __half2float(__float2half_rn((top * wv0 + bot * lv) * pe2));
    }
    {
        float top = a.w * wu0 + bq.w * lu;
        float bot = cq.w * wu0 + dq.w * lu;
        o.w = __half2float(__float2half_rn((top * wv0 + bot * lv) * pe3));
    }

    out[(size_t)p * 6 + j] = o;                  // fully coalesced 96B/point
}

extern "C" void kernel_launch(void* const* d_in, const int* in_sizes, int n_in,
                              void* d_out, int out_size) {
    // Bind inputs by size: grids has exactly 513*513*24 elements.
    int gi = -1, ci = -1;
    for (int i = 0; i < n_in; i++)
        if (in_sizes[i] == GRID_ELEMS && gi < 0) gi = i;
    for (int i = 0; i < n_in; i++)
        if (i != gi && ci < 0) ci = i;
    if (gi < 0) { gi = 1; ci = 0; }

    const float2* coords = (const float2*)d_in[ci];
    const float4* grids  = (const float4*)d_in[gi];
    float4*       out    = (float4*)d_out;
    int B = out_size / 24;                       // out is (B, 24) fp32
    long long threads_total = (long long)B * 6;
    int threads = 192;
    int blocks = (int)((threads_total + threads - 1) / threads);
    lpe2d_kernel<<<blocks, threads>>>(coords, grids, out, B);
}

// round 9
// speedup vs baseline: 1.5468x; 1.0313x over previous
#include <cuda_runtime.h>
#include <cuda_fp16.h>

// LocalPosEnc2D: bilinear grid sample (513x513 x 24ch, fp32) + sinusoidal PE gating.
//   coords: (B,2) fp32   grids: (513*513, 24) fp32   out: (B,24) fp32
// Warp-aligned cooperative layout: each warp owns exactly 5 points; lane
// l<30 handles point warp*5 + l/6, channel chunk l%6 (one float4 per corner
// row). No 6-lane group ever straddles a warp -> minimal L1 wavefronts.
// Trig: 2 MUFU (sin/cos of 2*pi*l folded to [-pi,pi)) + double-angle chain.

#define GRID_ELEMS (513 * 513 * 24)
#define TWO_PI_F 6.28318530717958647692f
#define PI_F     3.14159265358979323846f

__global__ __launch_bounds__(256) void lpe2d_kernel(
    const float2* __restrict__ coords,
    const float4* __restrict__ grids,   // grid row = 6 float4 (24 floats)
    float4*       __restrict__ out,     // out row  = 6 float4 (24 floats)
    int B)
{
    int gwarp = (blockIdx.x * blockDim.x + threadIdx.x) >> 5;
    int lane  = threadIdx.x & 31;
    if (lane >= 30) return;             // 2 idle lanes per warp (no straddle)
    int p = gwarp * 5 + lane / 6;       // point index
    int j = lane % 6;                   // chunk role 0..5 (channels 4j..4j+3)
    if (p >= B) return;

    float2 c = coords[p];               // 6 lanes same address -> broadcast
    float u = fminf(fmaxf(c.x, 0.0f), 1.0f - 1e-6f);
    float v = fminf(fmaxf(c.y, 0.0f), 1.0f - 1e-6f);
    float fu = u * 512.0f;
    float fv = v * 512.0f;
    int iu = (int)fu; iu = iu > 511 ? 511 : iu;
    int iv = (int)fv; iv = iv > 511 ? 511 : iv;
    float lu = fu - (float)iu;
    float lv = fv - (float)iv;

    int idx00 = iu + iv * 513;
    const float4* r0 = grids + (size_t)idx00 * 6;          // rows idx00, idx00+1 (192B)
    const float4* r1 = grids + (size_t)(idx00 + 513) * 6;  // rows idx01, idx01+1 (192B)

    // 4 independent 16B gathers; each LDG instruction covers 5 whole 96B
    // segments across the warp.
    float4 a  = r0[j];
    float4 bq = r0[j + 6];
    float4 cq = r1[j];
    float4 dq = r1[j + 6];

    // PE gates. Lane roles: j=0,1 base (gate 1);
    // j=2: cos(2^k*2pi*lu)  j=3: sin(..lu)  j=4: cos(..lv)  j=5: sin(..lv)
    float l = (j < 4) ? lu : lv;
    float ang = fmaf(l, TWO_PI_F, -PI_F);        // [-pi, pi)
    float s0 = -__sinf(ang);                     // sin(2*pi*l)
    float c0 = -__cosf(ang);                     // cos(2*pi*l)
    float s1 = 2.0f * s0 * c0;
    float c1 = fmaf(2.0f * c0, c0, -1.0f);
    float s2 = 2.0f * s1 * c1;
    float c2 = fmaf(2.0f * c1, c1, -1.0f);
    float s3 = 2.0f * s2 * c2;
    float c3 = fmaf(2.0f * c2, c2, -1.0f);

    bool use_sin = (j & 1);                      // j=3,5 -> sin ; j=2,4 -> cos
    float pe0 = use_sin ? s0 : c0;
    float pe1 = use_sin ? s1 : c1;
    float pe2 = use_sin ? s2 : c2;
    float pe3 = use_sin ? s3 : c3;
    if (j < 2) { pe0 = 1.0f; pe1 = 1.0f; pe2 = 1.0f; pe3 = 1.0f; }

    float wu0 = 1.0f - lu, wv0 = 1.0f - lv;

    float4 o;
    {
        float top = a.x * wu0 + bq.x * lu;
        float bot = cq.x * wu0 + dq.x * lu;
        o.x = __half2float(__float2half_rn((top * wv0 + bot * lv) * pe0));
    }
    {
        float top = a.y * wu0 + bq.y * lu;
        float bot = cq.y * wu0 + dq.y * lu;
        o.y = __half2float(__float2half_rn((top * wv0 + bot * lv) * pe1));
    }
    {
        float top = a.z * wu0 + bq.z * lu;
        float bot = cq.z * wu0 + dq.z * lu;
        o.z = __half2float(__float2half_rn((top * wv0 + bot * lv) * pe2));
    }
    {
        float top = a.w * wu0 + bq.w * lu;
        float bot = cq.w * wu0 + dq.w * lu;
        o.w = __half2float(__float2half_rn((top * wv0 + bot * lv) * pe3));
    }

    // Streaming store (evict-first): output is never re-read; keep the 25MB
    // grid table resident in L2 instead.
    __stcs(out + (size_t)p * 6 + j, o);
}

extern "C" void kernel_launch(void* const* d_in, const int* in_sizes, int n_in,
                              void* d_out, int out_size) {
    // Bind inputs by size: grids has exactly 513*513*24 elements.
    int gi = -1, ci = -1;
    for (int i = 0; i < n_in; i++)
        if (in_sizes[i] == GRID_ELEMS && gi < 0) gi = i;
    for (int i = 0; i < n_in; i++)
        if (i != gi && ci < 0) ci = i;
    if (gi < 0) { gi = 1; ci = 0; }

    const float2* coords = (const float2*)d_in[ci];
    const float4* grids  = (const float4*)d_in[gi];
    float4*       out    = (float4*)d_out;
    int B = out_size / 24;                         // out is (B, 24) fp32
    long long warps = ((long long)B + 4) / 5;      // 5 points per warp
    long long threads_total = warps * 32;
    int threads = 256;
    int blocks = (int)((threads_total + threads - 1) / threads);
    lpe2d_kernel<<<blocks, threads>>>(coords, grids, out, B);
}

// round 10
// speedup vs baseline: 1.7086x; 1.1047x over previous
#include <cuda_runtime.h>
#include <cuda_fp16.h>

// LocalPosEnc2D: bilinear grid sample (513x513 x 24ch, fp32) + sinusoidal PE gating.
//   coords: (B,2) fp32   grids: (513*513, 24) fp32   out: (B,24) fp32
// Warp-aligned cooperative layout, 2 points per thread for MLP=8:
// warp owns 10 points; lane l<30 -> role j=l%6 (channels 4j..4j+3), local
// q=l/6; handles points warp*10+q and warp*10+q+5. All 8 gathers issued
// before any use. Trig: 2 MUFU per point + double-angle chain.

#define GRID_ELEMS (513 * 513 * 24)
#define TWO_PI_F 6.28318530717958647692f
#define PI_F     3.14159265358979323846f

__device__ __forceinline__ void lpe_compute(
    float lu, float lv, int j,
    const float4& a, const float4& bq, const float4& cq, const float4& dq,
    float4& o)
{
    // PE gates. Lane roles: j=0,1 base (gate 1);
    // j=2: cos(2^k*2pi*lu)  j=3: sin(..lu)  j=4: cos(..lv)  j=5: sin(..lv)
    float l = (j < 4) ? lu : lv;
    float ang = fmaf(l, TWO_PI_F, -PI_F);        // [-pi, pi)
    float s0 = -__sinf(ang);                     // sin(2*pi*l)
    float c0 = -__cosf(ang);                     // cos(2*pi*l)
    float s1 = 2.0f * s0 * c0;
    float c1 = fmaf(2.0f * c0, c0, -1.0f);
    float s2 = 2.0f * s1 * c1;
    float c2 = fmaf(2.0f * c1, c1, -1.0f);
    float s3 = 2.0f * s2 * c2;
    float c3 = fmaf(2.0f * c2, c2, -1.0f);

    bool use_sin = (j & 1);
    float pe0 = use_sin ? s0 : c0;
    float pe1 = use_sin ? s1 : c1;
    float pe2 = use_sin ? s2 : c2;
    float pe3 = use_sin ? s3 : c3;
    if (j < 2) { pe0 = 1.0f; pe1 = 1.0f; pe2 = 1.0f; pe3 = 1.0f; }

    float wu0 = 1.0f - lu, wv0 = 1.0f - lv;

    float t0, b0;
    t0 = a.x * wu0 + bq.x * lu;  b0 = cq.x * wu0 + dq.x * lu;
    o.x = __half2float(__float2half_rn((t0 * wv0 + b0 * lv) * pe0));
    t0 = a.y * wu0 + bq.y * lu;  b0 = cq.y * wu0 + dq.y * lu;
    o.y = __half2float(__float2half_rn((t0 * wv0 + b0 * lv) * pe1));
    t0 = a.z * wu0 + bq.z * lu;  b0 = cq.z * wu0 + dq.z * lu;
    o.z = __half2float(__float2half_rn((t0 * wv0 + b0 * lv) * pe2));
    t0 = a.w * wu0 + bq.w * lu;  b0 = cq.w * wu0 + dq.w * lu;
    o.w = __half2float(__float2half_rn((t0 * wv0 + b0 * lv) * pe3));
}

__device__ __forceinline__ void setup_point(
    const float2& c, float& lu, float& lv, int& idx00)
{
    float u = fminf(fmaxf(c.x, 0.0f), 1.0f - 1e-6f);
    float v = fminf(fmaxf(c.y, 0.0f), 1.0f - 1e-6f);
    float fu = u * 512.0f;
    float fv = v * 512.0f;
    int iu = (int)fu; iu = iu > 511 ? 511 : iu;
    int iv = (int)fv; iv = iv > 511 ? 511 : iv;
    lu = fu - (float)iu;
    lv = fv - (float)iv;
    idx00 = iu + iv * 513;
}

__global__ __launch_bounds__(256) void lpe2d_kernel(
    const float2* __restrict__ coords,
    const float4* __restrict__ grids,   // grid row = 6 float4 (24 floats)
    float4*       __restrict__ out,     // out row  = 6 float4 (24 floats)
    int B)
{
    int gwarp = (blockIdx.x * blockDim.x + threadIdx.x) >> 5;
    int lane  = threadIdx.x & 31;
    if (lane >= 30) return;             // 2 idle lanes per warp (no straddle)
    int q = lane / 6;                   // local point 0..4
    int j = lane - q * 6;               // chunk role 0..5

    int p0 = gwarp * 10 + q;
    int p1 = p0 + 5;
    if (p0 >= B) return;
    bool has1 = (p1 < B);

    // Coord loads (broadcast within each 6-lane group).
    float2 c0 = coords[p0];
    float2 c1 = coords[has1 ? p1 : p0];  // clamp: keep addresses valid, no divergence

    float lu0, lv0, lu1, lv1;
    int i0, i1;
    setup_point(c0, lu0, lv0, i0);
    setup_point(c1, lu1, lv1, i1);

    const float4* r00 = grids + (size_t)i0 * 6;          // p0 rows iv,   (192B)
    const float4* r01 = grids + (size_t)(i0 + 513) * 6;  // p0 rows iv+1
    const float4* r10 = grids + (size_t)i1 * 6;
    const float4* r11 = grids + (size_t)(i1 + 513) * 6;

    // Issue all 8 gathers before any use (MLP=8).
    float4 a0 = r00[j];
    float4 b0 = r00[j + 6];
    float4 c0g = r01[j];
    float4 d0 = r01[j + 6];
    float4 a1 = r10[j];
    float4 b1 = r10[j + 6];
    float4 c1g = r11[j];
    float4 d1 = r11[j + 6];

    float4 o0, o1;
    lpe_compute(lu0, lv0, j, a0, b0, c0g, d0, o0);
    lpe_compute(lu1, lv1, j, a1, b1, c1g, d1, o1);

    // Streaming stores (evict-first): output never re-read; preserve the
    // 25MB grid table's L2 residency.
    __stcs(out + (size_t)p0 * 6 + j, o0);
    if (has1) __stcs(out + (size_t)p1 * 6 + j, o1);
}

extern "C" void kernel_launch(void* const* d_in, const int* in_sizes, int n_in,
                              void* d_out, int out_size) {
    // Bind inputs by size: grids has exactly 513*513*24 elements.
    int gi = -1, ci = -1;
    for (int i = 0; i < n_in; i++)
        if (in_sizes[i] == GRID_ELEMS && gi < 0) gi = i;
    for (int i = 0; i < n_in; i++)
        if (i != gi && ci < 0) ci = i;
    if (gi < 0) { gi = 1; ci = 0; }

    const float2* coords = (const float2*)d_in[ci];
    const float4* grids  = (const float4*)d_in[gi];
    float4*       out    = (float4*)d_out;
    int B = out_size / 24;                          // out is (B, 24) fp32
    long long warps = ((long long)B + 9) / 10;      // 10 points per warp
    long long threads_total = warps * 32;
    int threads = 256;
    int blocks = (int)((threads_total + threads - 1) / threads);
    lpe2d_kernel<<<blocks, threads>>>(coords, grids, out, B);
}